// round 15
// baseline (speedup 1.0000x reference)
#include <cuda_runtime.h>
#include <cuda_fp16.h>
#include <cstdint>

// NTXentLoss N=8192, D=128 fp32.
// loss = mean_i( log(sum_{j!=i} exp(10*cos(i,j))) - 10*cos(i, i^4096) )
// fp16 HMMA with FP16 ACCUMULATORS (mma.sync.m16n8k16.f16) — accumulator is the
// log2-domain logit directly (temperature folded: g_h = sqrt(10*log2 e) * z),
// exponentiated in-register via ex2.approx.f16x2 with zero conversions.
// Symmetric upper-triangle tiles (2080 of 128x128), chunked over 296 CTAs with
// A-reuse + B double-buffer prefetch. Positive-pair cos exact fp32 in normalize.

#define NN 8192
#define DD 128
#define ROWB 272               // padded smem row: 256 B (128 halves) + 16 pad
#define TILEB (128 * ROWB)     // 34816 B per 128x128 fp16 tile
#define GRID_MAIN 296          // 148 SMs x 2 CTAs
#define EXK 14.4269504088896340736f    // 10 * log2(e)
#define SQEXK 3.7982825f               // sqrt(EXK)

__device__ __half g_h[NN * DD];        // sqrt(EXK)-scaled normalized fp16 [n][k]
__device__ float  g_sumE[NN];          // exp-sum accumulators
__device__ float  g_pos[NN / 2];       // exact cos(i, i+4096) per pair

__device__ __forceinline__ uint32_t smem_u32(const void* p) {
    return (uint32_t)__cvta_generic_to_shared(p);
}
__device__ __forceinline__ void cp16(uint32_t dst, const void* src) {
    asm volatile("cp.async.cg.shared.global [%0], [%1], 16;\n" :: "r"(dst), "l"(src));
}
__device__ __forceinline__ float ex2f(float x) {
    float r; asm("ex2.approx.f32 %0, %1;" : "=f"(r) : "f"(x)); return r;
}
__device__ __forceinline__ uint32_t ex2h2u(uint32_t x) {
    uint32_t r;
    asm("ex2.approx.f16x2 %0, %1;" : "=r"(r) : "r"(x));
    return r;
}
__device__ __forceinline__ void ldsm_x4(uint32_t a, uint32_t r[4]) {
    asm volatile("ldmatrix.sync.aligned.m8n8.x4.shared.b16 {%0,%1,%2,%3}, [%4];"
                 : "=r"(r[0]), "=r"(r[1]), "=r"(r[2]), "=r"(r[3]) : "r"(a));
}
// m16n8k16 with fp16 accumulators: D/C are 2 regs, each half2 of ADJACENT cols:
// d0 = (row, col),(row, col+1); d1 = (row+8, col),(row+8, col+1)
__device__ __forceinline__ void mma16816h(uint32_t c[2], const uint32_t a[4],
                                          const uint32_t b[2]) {
    asm volatile(
        "mma.sync.aligned.m16n8k16.row.col.f16.f16.f16.f16 "
        "{%0,%1}, {%2,%3,%4,%5}, {%6,%7}, {%0,%1};"
        : "+r"(c[0]), "+r"(c[1])
        : "r"(a[0]), "r"(a[1]), "r"(a[2]), "r"(a[3]), "r"(b[0]), "r"(b[1]));
}

// Triangle decode: f -> (I, J), J >= I.
__device__ __forceinline__ void decodeIJ(int f, int& I, int& J) {
    int i = (int)((129.0f - sqrtf(16641.0f - 8.0f * (float)f)) * 0.5f);
    while (64 * (i + 1) - ((i + 1) * i) / 2 <= f) ++i;
    while (64 * i - (i * (i - 1)) / 2 > f) --i;
    I = i;
    J = i + (f - (64 * i - (i * (i - 1)) / 2));
}

// ---------------------------------------------------------------------------
// Phase 1: one PAIR per warp. Normalize, emit sqrt(EXK)*z in fp16; exact fp32
// positive-pair cosine via the same shfl pass. Zero accumulators.
// ---------------------------------------------------------------------------
__global__ void __launch_bounds__(256) nt_normalize(const float* __restrict__ x,
                                                    float* __restrict__ out) {
    const int lane = threadIdx.x & 31;
    const int p = blockIdx.x * 8 + (threadIdx.x >> 5);    // pair id 0..4095
    const int r0 = p, r1 = p + NN / 2;
    const float4 v0 = reinterpret_cast<const float4*>(x)[r0 * 32 + lane];
    const float4 v1 = reinterpret_cast<const float4*>(x)[r1 * 32 + lane];
    float s0 = v0.x * v0.x + v0.y * v0.y + v0.z * v0.z + v0.w * v0.w;
    float s1 = v1.x * v1.x + v1.y * v1.y + v1.z * v1.z + v1.w * v1.w;
    float d  = v0.x * v1.x + v0.y * v1.y + v0.z * v1.z + v0.w * v1.w;
#pragma unroll
    for (int o = 16; o; o >>= 1) {
        s0 += __shfl_xor_sync(0xffffffffu, s0, o);
        s1 += __shfl_xor_sync(0xffffffffu, s1, o);
        d  += __shfl_xor_sync(0xffffffffu, d, o);
    }
    const float i0 = 1.0f / fmaxf(sqrtf(s0), 1e-8f);
    const float i1 = 1.0f / fmaxf(sqrtf(s1), 1e-8f);
    const float q0 = i0 * SQEXK, q1 = i1 * SQEXK;
    __half2* h0 = reinterpret_cast<__half2*>(g_h) + r0 * 64 + lane * 2;
    __half2* h1 = reinterpret_cast<__half2*>(g_h) + r1 * 64 + lane * 2;
    h0[0] = __floats2half2_rn(v0.x * q0, v0.y * q0);
    h0[1] = __floats2half2_rn(v0.z * q0, v0.w * q0);
    h1[0] = __floats2half2_rn(v1.x * q1, v1.y * q1);
    h1[1] = __floats2half2_rn(v1.z * q1, v1.w * q1);
    if (lane == 0) {
        g_pos[p] = d * i0 * i1;          // exact cos of the positive pair
        g_sumE[r0] = 0.0f;
        g_sumE[r1] = 0.0f;
        if (p == 0) out[0] = 0.0f;
    }
}

// Load one [128 samples][128 halves] tile into padded smem (272B rows).
__device__ __forceinline__ void load_tile(uint32_t sdst, int sbase, int tid) {
#pragma unroll
    for (int i = 0; i < 8; ++i) {          // 2048 x 16B / 256 threads
        const int f = tid + (i << 8);
        const int row = f >> 4, kb = f & 15;
        cp16(sdst + row * ROWB + (kb << 4),
             (const char*)g_h + ((size_t)(sbase + row) << 8) + (kb << 4));
    }
}

// ---------------------------------------------------------------------------
// Phase 2: chunked triangle tiles, A reused, B double-buffered (R10 mainloop);
// fp16-accumulator MMA + in-register f16x2 exp epilogue (no conversions).
// ---------------------------------------------------------------------------
__global__ void __launch_bounds__(256, 2) nt_main() {
    extern __shared__ char sm[];
    __shared__ float s_rowP[4][128];
    __shared__ float s_colP[2][128];

    const int tid = threadIdx.x, wid = tid >> 5, lane = tid & 31;
    const int wM = wid >> 2, wN = wid & 3;
    const uint32_t aBase = smem_u32(sm);
    const uint32_t bB[2] = {aBase + TILEB, aBase + 2 * TILEB};

    const int w = blockIdx.x;
    const int cnt = 7 + (w < 8 ? 1 : 0);
    const int start = w * 7 + (w < 8 ? w : 8);

    int I, J;
    decodeIJ(start, I, J);
    load_tile(aBase, I * 128, tid);
    if (J != I) load_tile(bB[0], J * 128, tid);
    asm volatile("cp.async.commit_group;\n");
    int cur = 0;

    const uint32_t aLane = (uint32_t)((wM * 64 + (lane & 15)) * ROWB + ((lane >> 4) << 4));
    const uint32_t bLane = (uint32_t)((wN * 32 + ((lane >> 4) << 3) + (lane & 7)) * ROWB
                                      + (((lane >> 3) & 1) << 4));

    for (int k = 0; k < cnt; ++k) {
        const bool diag = (I == J);
        const int rowBase = I * 128, colBase = J * 128;
        const uint32_t bBase = diag ? aBase : bB[cur];

        asm volatile("cp.async.wait_group 0;\n" ::: "memory");
        __syncthreads();

        const bool havenext = (k + 1 < cnt);
        const bool rowChange = havenext && (J == 63);
        const bool preB = havenext && !rowChange;
        if (preB) {
            load_tile(bB[cur ^ 1], (J + 1) * 128, tid);
            asm volatile("cp.async.commit_group;\n");
        }

        uint32_t c[4][4][2];     // fp16x2 accumulators
#pragma unroll
        for (int mf = 0; mf < 4; ++mf)
#pragma unroll
            for (int nf = 0; nf < 4; ++nf) { c[mf][nf][0] = 0u; c[mf][nf][1] = 0u; }

#pragma unroll
        for (int ks = 0; ks < 8; ++ks) {
            uint32_t a[4][4], b[4][2];
#pragma unroll
            for (int mf = 0; mf < 4; ++mf)
                ldsm_x4(aBase + aLane + (uint32_t)(mf * 16 * ROWB) + (ks << 5), a[mf]);
#pragma unroll
            for (int np = 0; np < 2; ++np) {
                uint32_t r4[4];
                ldsm_x4(bBase + bLane + (uint32_t)(np * 16 * ROWB) + (ks << 5), r4);
                b[2 * np][0] = r4[0]; b[2 * np][1] = r4[1];
                b[2 * np + 1][0] = r4[2]; b[2 * np + 1][1] = r4[3];
            }
#pragma unroll
            for (int mf = 0; mf < 4; ++mf)
#pragma unroll
                for (int nf = 0; nf < 4; ++nf)
                    mma16816h(c[mf][nf], a[mf], b[nf]);
        }

        // Epilogue: acc holds EXK*cos as f16x2 (adjacent cols). Direct ex2.
        const int thRow0 = rowBase + wM * 64 + (lane >> 2);
        const int thCol0 = wN * 32 + ((lane & 3) << 1);
        float sE[8], cS[8];

        if (diag) {   // exact-ish masked path via f32 conversion (64 tiles)
#pragma unroll
            for (int i = 0; i < 8; ++i) { sE[i] = 0.0f; cS[i] = 0.0f; }
#pragma unroll
            for (int mf = 0; mf < 4; ++mf)
#pragma unroll
                for (int nf = 0; nf < 4; ++nf)
#pragma unroll
                    for (int rh = 0; rh < 2; ++rh) {
                        const float2 f = __half22float2(
                            *reinterpret_cast<const __half2*>(&c[mf][nf][rh]));
                        const int row = thRow0 + mf * 16 + rh * 8;
                        const int c0 = colBase + thCol0 + nf * 8;
                        sE[mf * 2 + rh] += (c0 == row) ? 0.0f : ex2f(f.x);
                        sE[mf * 2 + rh] += (c0 + 1 == row) ? 0.0f : ex2f(f.y);
                    }
        } else {      // 1 mufu + 2 hadd2 per 2 elements, zero conversions
            __half2 sEh[8], cSh[4];
            const __half2 hz = __float2half2_rn(0.0f);
#pragma unroll
            for (int i = 0; i < 8; ++i) sEh[i] = hz;
#pragma unroll
            for (int i = 0; i < 4; ++i) cSh[i] = hz;
#pragma unroll
            for (int mf = 0; mf < 4; ++mf)
#pragma unroll
                for (int nf = 0; nf < 4; ++nf)
#pragma unroll
                    for (int rh = 0; rh < 2; ++rh) {
                        const uint32_t eu = ex2h2u(c[mf][nf][rh]);
                        const __half2 e = *reinterpret_cast<const __half2*>(&eu);
                        sEh[mf * 2 + rh] = __hadd2(sEh[mf * 2 + rh], e);
                        cSh[nf] = __hadd2(cSh[nf], e);
                    }
#pragma unroll
            for (int i = 0; i < 8; ++i) {
                const float2 f = __half22float2(sEh[i]);
                sE[i] = f.x + f.y;
            }
#pragma unroll
            for (int i = 0; i < 4; ++i) {
                const float2 f = __half22float2(cSh[i]);
                cS[2 * i] = f.x;
                cS[2 * i + 1] = f.y;
            }
        }

#pragma unroll
        for (int i = 0; i < 8; ++i) {
            sE[i] += __shfl_xor_sync(0xffffffffu, sE[i], 1);
            sE[i] += __shfl_xor_sync(0xffffffffu, sE[i], 2);
        }
        if (!diag) {
#pragma unroll
            for (int i = 0; i < 8; ++i) {
                cS[i] += __shfl_xor_sync(0xffffffffu, cS[i], 4);
                cS[i] += __shfl_xor_sync(0xffffffffu, cS[i], 8);
                cS[i] += __shfl_xor_sync(0xffffffffu, cS[i], 16);
            }
        }

        if ((lane & 3) == 0) {
            const int r0 = wM * 64 + (lane >> 2);
#pragma unroll
            for (int i = 0; i < 8; ++i)
                s_rowP[wN][r0 + (i >> 1) * 16 + (i & 1) * 8] = sE[i];
        }
        if (!diag && lane < 4) {
#pragma unroll
            for (int i = 0; i < 8; ++i)
                s_colP[wM][wN * 32 + (i >> 1) * 8 + lane * 2 + (i & 1)] = cS[i];
        }
        __syncthreads();

        if (tid < 128) {
            const float rs = s_rowP[0][tid] + s_rowP[1][tid]
                           + s_rowP[2][tid] + s_rowP[3][tid];
            atomicAdd(&g_sumE[rowBase + tid], rs);
            if (!diag) {
                const float cs = s_colP[0][tid] + s_colP[1][tid];
                atomicAdd(&g_sumE[colBase + tid], cs);
            }
        }

        if (rowChange) {
            load_tile(aBase, (I + 1) * 128, tid);
            asm volatile("cp.async.commit_group;\n");
            ++I; J = I;
        } else if (preB) {
            ++J; cur ^= 1;
        }
    }
}

// ---------------------------------------------------------------------------
// Phase 3: 16 CTAs, one pair per thread; loss mean from sumE + precomputed pos.
// ---------------------------------------------------------------------------
__global__ void __launch_bounds__(256) nt_final(float* __restrict__ out) {
    const int p = blockIdx.x * 256 + threadIdx.x;        // pair id (grid 16)
    float v = __logf(g_sumE[p]) + __logf(g_sumE[p + NN / 2]) - 20.0f * g_pos[p];
#pragma unroll
    for (int o = 16; o; o >>= 1) v += __shfl_xor_sync(0xffffffffu, v, o);
    __shared__ float ws[8];
    if ((threadIdx.x & 31) == 0) ws[threadIdx.x >> 5] = v;
    __syncthreads();
    if (threadIdx.x == 0) {
        float s = 0.0f;
#pragma unroll
        for (int i = 0; i < 8; ++i) s += ws[i];
        atomicAdd(out, s * (1.0f / NN));
    }
}

// ---------------------------------------------------------------------------
extern "C" void kernel_launch(void* const* d_in, const int* in_sizes, int n_in,
                              void* d_out, int out_size) {
    (void)in_sizes; (void)n_in; (void)out_size;
    const float* x = (const float*)d_in[0];
    float* out = (float*)d_out;

    nt_normalize<<<NN / 16, 256>>>(x, out);

    const int smem = 3 * TILEB;   // 104448 B (A + 2x B)
    cudaFuncSetAttribute(nt_main, cudaFuncAttributeMaxDynamicSharedMemorySize, smem);
    nt_main<<<GRID_MAIN, 256, smem>>>();

    nt_final<<<16, 256>>>(out);
}

// round 16
// speedup vs baseline: 1.1687x; 1.1687x over previous
#include <cuda_runtime.h>
#include <cuda_fp16.h>
#include <cstdint>

// NTXentLoss N=8192, D=128 fp32.
// loss = mean_i( log(sum_{j!=i} exp(10*cos(i,j))) - 10*cos(i, i^4096) )
// fp16 HMMA f32-acc (mma.sync.m16n8k16) — fastest matmul primitive reachable at
// this PTX target (f16-acc, int8, fp8 all measured rate-demoted on sm_103).
// Symmetric upper-triangle tiles (2080 of 128x128) chunked over 296 CTAs with
// A-reuse + B double-buffer. Temperature folded: g_h = sqrt(10*log2 e) * z so
// acc = log2-domain logit; epilogue exp via ex2.approx.f16x2.
// Loss reduction runs in the LAST nt_main CTA (done-counter) — no third launch.

#define NN 8192
#define DD 128
#define ROWB 272               // padded smem row: 256 B (128 halves) + 16 pad
#define TILEB (128 * ROWB)     // 34816 B per 128x128 fp16 tile
#define GRID_MAIN 296          // 148 SMs x 2 CTAs
#define EXK 14.4269504088896340736f    // 10 * log2(e)
#define SQEXK 3.7982825f               // sqrt(EXK)

__device__ __half    g_h[NN * DD];     // sqrt(EXK)-scaled normalized fp16 [n][k]
__device__ float     g_sumE[NN];       // exp-sum accumulators
__device__ float     g_pos[NN / 2];    // exact cos(i, i+4096) per pair
__device__ unsigned  g_done = 0;       // completion counter (last-CTA detect)

__device__ __forceinline__ uint32_t smem_u32(const void* p) {
    return (uint32_t)__cvta_generic_to_shared(p);
}
__device__ __forceinline__ void cp16(uint32_t dst, const void* src) {
    asm volatile("cp.async.cg.shared.global [%0], [%1], 16;\n" :: "r"(dst), "l"(src));
}
__device__ __forceinline__ float ex2f(float x) {
    float r; asm("ex2.approx.f32 %0, %1;" : "=f"(r) : "f"(x)); return r;
}
__device__ __forceinline__ uint32_t ex2h2u(uint32_t x) {
    uint32_t r;
    asm("ex2.approx.f16x2 %0, %1;" : "=r"(r) : "r"(x));
    return r;
}
__device__ __forceinline__ void ldsm_x4(uint32_t a, uint32_t r[4]) {
    asm volatile("ldmatrix.sync.aligned.m8n8.x4.shared.b16 {%0,%1,%2,%3}, [%4];"
                 : "=r"(r[0]), "=r"(r[1]), "=r"(r[2]), "=r"(r[3]) : "r"(a));
}
__device__ __forceinline__ void mma16816(float c[4], const uint32_t a[4],
                                         const uint32_t b[2]) {
    asm volatile(
        "mma.sync.aligned.m16n8k16.row.col.f32.f16.f16.f32 "
        "{%0,%1,%2,%3}, {%4,%5,%6,%7}, {%8,%9}, {%0,%1,%2,%3};"
        : "+f"(c[0]), "+f"(c[1]), "+f"(c[2]), "+f"(c[3])
        : "r"(a[0]), "r"(a[1]), "r"(a[2]), "r"(a[3]), "r"(b[0]), "r"(b[1]));
}

// Triangle decode: f -> (I, J), J >= I.
__device__ __forceinline__ void decodeIJ(int f, int& I, int& J) {
    int i = (int)((129.0f - sqrtf(16641.0f - 8.0f * (float)f)) * 0.5f);
    while (64 * (i + 1) - ((i + 1) * i) / 2 <= f) ++i;
    while (64 * i - (i * (i - 1)) / 2 > f) --i;
    I = i;
    J = i + (f - (64 * i - (i * (i - 1)) / 2));
}

// ---------------------------------------------------------------------------
// Phase 1: TWO pairs per warp, all loads up front (ILP), 6 interleaved shfl
// chains. Emits sqrt(EXK)*z fp16 + exact fp32 pair cosines; zeros accumulators.
// ---------------------------------------------------------------------------
__global__ void __launch_bounds__(256) nt_normalize(const float* __restrict__ x) {
    const int lane = threadIdx.x & 31;
    const int pw = blockIdx.x * 8 + (threadIdx.x >> 5);   // warp id 0..2047
    const int pA = pw * 2, pB = pw * 2 + 1;               // two pairs
    const float4 a0 = reinterpret_cast<const float4*>(x)[pA * 32 + lane];
    const float4 a1 = reinterpret_cast<const float4*>(x)[(pA + NN / 2) * 32 + lane];
    const float4 b0 = reinterpret_cast<const float4*>(x)[pB * 32 + lane];
    const float4 b1 = reinterpret_cast<const float4*>(x)[(pB + NN / 2) * 32 + lane];
    float sA0 = a0.x * a0.x + a0.y * a0.y + a0.z * a0.z + a0.w * a0.w;
    float sA1 = a1.x * a1.x + a1.y * a1.y + a1.z * a1.z + a1.w * a1.w;
    float dA  = a0.x * a1.x + a0.y * a1.y + a0.z * a1.z + a0.w * a1.w;
    float sB0 = b0.x * b0.x + b0.y * b0.y + b0.z * b0.z + b0.w * b0.w;
    float sB1 = b1.x * b1.x + b1.y * b1.y + b1.z * b1.z + b1.w * b1.w;
    float dB  = b0.x * b1.x + b0.y * b1.y + b0.z * b1.z + b0.w * b1.w;
#pragma unroll
    for (int o = 16; o; o >>= 1) {
        sA0 += __shfl_xor_sync(0xffffffffu, sA0, o);
        sA1 += __shfl_xor_sync(0xffffffffu, sA1, o);
        dA  += __shfl_xor_sync(0xffffffffu, dA, o);
        sB0 += __shfl_xor_sync(0xffffffffu, sB0, o);
        sB1 += __shfl_xor_sync(0xffffffffu, sB1, o);
        dB  += __shfl_xor_sync(0xffffffffu, dB, o);
    }
    const float iA0 = 1.0f / fmaxf(sqrtf(sA0), 1e-8f);
    const float iA1 = 1.0f / fmaxf(sqrtf(sA1), 1e-8f);
    const float iB0 = 1.0f / fmaxf(sqrtf(sB0), 1e-8f);
    const float iB1 = 1.0f / fmaxf(sqrtf(sB1), 1e-8f);
    const float qA0 = iA0 * SQEXK, qA1 = iA1 * SQEXK;
    const float qB0 = iB0 * SQEXK, qB1 = iB1 * SQEXK;
    __half2* h;
    h = reinterpret_cast<__half2*>(g_h) + pA * 64 + lane * 2;
    h[0] = __floats2half2_rn(a0.x * qA0, a0.y * qA0);
    h[1] = __floats2half2_rn(a0.z * qA0, a0.w * qA0);
    h = reinterpret_cast<__half2*>(g_h) + (pA + NN / 2) * 64 + lane * 2;
    h[0] = __floats2half2_rn(a1.x * qA1, a1.y * qA1);
    h[1] = __floats2half2_rn(a1.z * qA1, a1.w * qA1);
    h = reinterpret_cast<__half2*>(g_h) + pB * 64 + lane * 2;
    h[0] = __floats2half2_rn(b0.x * qB0, b0.y * qB0);
    h[1] = __floats2half2_rn(b0.z * qB0, b0.w * qB0);
    h = reinterpret_cast<__half2*>(g_h) + (pB + NN / 2) * 64 + lane * 2;
    h[0] = __floats2half2_rn(b1.x * qB1, b1.y * qB1);
    h[1] = __floats2half2_rn(b1.z * qB1, b1.w * qB1);
    if (lane == 0) {
        g_pos[pA] = dA * iA0 * iA1;
        g_pos[pB] = dB * iB0 * iB1;
        g_sumE[pA] = 0.0f; g_sumE[pA + NN / 2] = 0.0f;
        g_sumE[pB] = 0.0f; g_sumE[pB + NN / 2] = 0.0f;
    }
}

// Load one [128 samples][128 halves] tile into padded smem (272B rows).
__device__ __forceinline__ void load_tile(uint32_t sdst, int sbase, int tid) {
#pragma unroll
    for (int i = 0; i < 8; ++i) {          // 2048 x 16B / 256 threads
        const int f = tid + (i << 8);
        const int row = f >> 4, kb = f & 15;
        cp16(sdst + row * ROWB + (kb << 4),
             (const char*)g_h + ((size_t)(sbase + row) << 8) + (kb << 4));
    }
}

// ---------------------------------------------------------------------------
// Phase 2: chunked triangle tiles (R14 mainloop, f32-acc MMA + f16x2 exp).
// The LAST CTA to finish also performs the loss reduction (phase 3).
// ---------------------------------------------------------------------------
__global__ void __launch_bounds__(256, 2) nt_main(float* __restrict__ out) {
    extern __shared__ char sm[];
    __shared__ float s_rowP[4][128];
    __shared__ float s_colP[2][128];
    __shared__ unsigned s_rank;

    const int tid = threadIdx.x, wid = tid >> 5, lane = tid & 31;
    const int wM = wid >> 2, wN = wid & 3;
    const uint32_t aBase = smem_u32(sm);
    const uint32_t bB[2] = {aBase + TILEB, aBase + 2 * TILEB};

    const int w = blockIdx.x;
    const int cnt = 7 + (w < 8 ? 1 : 0);
    const int start = w * 7 + (w < 8 ? w : 8);

    int I, J;
    decodeIJ(start, I, J);
    load_tile(aBase, I * 128, tid);
    if (J != I) load_tile(bB[0], J * 128, tid);
    asm volatile("cp.async.commit_group;\n");
    int cur = 0;

    const uint32_t aLane = (uint32_t)((wM * 64 + (lane & 15)) * ROWB + ((lane >> 4) << 4));
    const uint32_t bLane = (uint32_t)((wN * 32 + ((lane >> 4) << 3) + (lane & 7)) * ROWB
                                      + (((lane >> 3) & 1) << 4));

    for (int k = 0; k < cnt; ++k) {
        const bool diag = (I == J);
        const int rowBase = I * 128, colBase = J * 128;
        const uint32_t bBase = diag ? aBase : bB[cur];

        asm volatile("cp.async.wait_group 0;\n" ::: "memory");
        __syncthreads();

        const bool havenext = (k + 1 < cnt);
        const bool rowChange = havenext && (J == 63);
        const bool preB = havenext && !rowChange;
        if (preB) {
            load_tile(bB[cur ^ 1], (J + 1) * 128, tid);
            asm volatile("cp.async.commit_group;\n");
        }

        float c[4][4][4];
#pragma unroll
        for (int mf = 0; mf < 4; ++mf)
#pragma unroll
            for (int nf = 0; nf < 4; ++nf)
#pragma unroll
                for (int r = 0; r < 4; ++r) c[mf][nf][r] = 0.0f;

#pragma unroll
        for (int ks = 0; ks < 8; ++ks) {
            uint32_t a[4][4], b[4][2];
#pragma unroll
            for (int mf = 0; mf < 4; ++mf)
                ldsm_x4(aBase + aLane + (uint32_t)(mf * 16 * ROWB) + (ks << 5), a[mf]);
#pragma unroll
            for (int np = 0; np < 2; ++np) {
                uint32_t r4[4];
                ldsm_x4(bBase + bLane + (uint32_t)(np * 16 * ROWB) + (ks << 5), r4);
                b[2 * np][0] = r4[0]; b[2 * np][1] = r4[1];
                b[2 * np + 1][0] = r4[2]; b[2 * np + 1][1] = r4[3];
            }
#pragma unroll
            for (int mf = 0; mf < 4; ++mf)
#pragma unroll
                for (int nf = 0; nf < 4; ++nf)
                    mma16816(c[mf][nf], a[mf], b[nf]);
        }

        // Epilogue: acc is EXK*cos (log2-domain logit).
        const int thRow0 = rowBase + wM * 64 + (lane >> 2);
        const int thCol0 = wN * 32 + ((lane & 3) << 1);
        float sE[8], cS[8];

        if (diag) {   // exact fp32 masked path (64 of 2080 tiles)
#pragma unroll
            for (int i = 0; i < 8; ++i) { sE[i] = 0.0f; cS[i] = 0.0f; }
#pragma unroll
            for (int mf = 0; mf < 4; ++mf)
#pragma unroll
                for (int nf = 0; nf < 4; ++nf)
#pragma unroll
                    for (int r = 0; r < 4; ++r) {
                        const int row = thRow0 + mf * 16 + ((r >> 1) << 3);
                        const int col = colBase + thCol0 + nf * 8 + (r & 1);
                        const float e = (col == row) ? 0.0f : ex2f(c[mf][nf][r]);
                        sE[mf * 2 + (r >> 1)] += e;
                    }
        } else {      // f16x2: 1 cvt + 1 mufu + 2 hadd2 per 2 elements
            const __half2 hz = __float2half2_rn(0.0f);
            __half2 sEh[8], cSh[4];
#pragma unroll
            for (int i = 0; i < 8; ++i) sEh[i] = hz;
#pragma unroll
            for (int i = 0; i < 4; ++i) cSh[i] = hz;
#pragma unroll
            for (int mf = 0; mf < 4; ++mf)
#pragma unroll
                for (int nf = 0; nf < 4; ++nf)
#pragma unroll
                    for (int rh = 0; rh < 2; ++rh) {
                        const __half2 hv = __floats2half2_rn(c[mf][nf][2 * rh],
                                                             c[mf][nf][2 * rh + 1]);
                        const uint32_t eu =
                            ex2h2u(*reinterpret_cast<const uint32_t*>(&hv));
                        const __half2 e = *reinterpret_cast<const __half2*>(&eu);
                        sEh[mf * 2 + rh] = __hadd2(sEh[mf * 2 + rh], e);
                        cSh[nf] = __hadd2(cSh[nf], e);
                    }
#pragma unroll
            for (int i = 0; i < 8; ++i) {
                const float2 f = __half22float2(sEh[i]);
                sE[i] = f.x + f.y;
            }
#pragma unroll
            for (int i = 0; i < 4; ++i) {
                const float2 f = __half22float2(cSh[i]);
                cS[2 * i] = f.x;
                cS[2 * i + 1] = f.y;
            }
        }

#pragma unroll
        for (int i = 0; i < 8; ++i) {
            sE[i] += __shfl_xor_sync(0xffffffffu, sE[i], 1);
            sE[i] += __shfl_xor_sync(0xffffffffu, sE[i], 2);
        }
        if (!diag) {
#pragma unroll
            for (int i = 0; i < 8; ++i) {
                cS[i] += __shfl_xor_sync(0xffffffffu, cS[i], 4);
                cS[i] += __shfl_xor_sync(0xffffffffu, cS[i], 8);
                cS[i] += __shfl_xor_sync(0xffffffffu, cS[i], 16);
            }
        }

        if ((lane & 3) == 0) {
            const int r0 = wM * 64 + (lane >> 2);
#pragma unroll
            for (int i = 0; i < 8; ++i)
                s_rowP[wN][r0 + (i >> 1) * 16 + (i & 1) * 8] = sE[i];
        }
        if (!diag && lane < 4) {
#pragma unroll
            for (int i = 0; i < 8; ++i)
                s_colP[wM][wN * 32 + (i >> 1) * 8 + lane * 2 + (i & 1)] = cS[i];
        }
        __syncthreads();

        if (tid < 128) {
            const float rs = s_rowP[0][tid] + s_rowP[1][tid]
                           + s_rowP[2][tid] + s_rowP[3][tid];
            atomicAdd(&g_sumE[rowBase + tid], rs);
            if (!diag) {
                const float cs = s_colP[0][tid] + s_colP[1][tid];
                atomicAdd(&g_sumE[colBase + tid], cs);
            }
        }

        if (rowChange) {
            load_tile(aBase, (I + 1) * 128, tid);
            asm volatile("cp.async.commit_group;\n");
            ++I; J = I;
        } else if (preB) {
            ++J; cur ^= 1;
        }
    }

    // ---------------- Last-CTA loss reduction (replaces third launch) -------
    __syncthreads();
    __threadfence();                        // order g_sumE atomics before counter
    if (tid == 0) s_rank = atomicAdd(&g_done, 1u);
    __syncthreads();
    if (s_rank == GRID_MAIN - 1) {
        float acc = 0.0f;
#pragma unroll 4
        for (int it = 0; it < 16; ++it) {
            const int p = it * 256 + tid;   // pair id 0..4095
            acc += __logf(__ldcg(&g_sumE[p])) + __logf(__ldcg(&g_sumE[p + NN / 2]))
                 - 20.0f * __ldcg(&g_pos[p]);
        }
#pragma unroll
        for (int o = 16; o; o >>= 1) acc += __shfl_xor_sync(0xffffffffu, acc, o);
        if (lane == 0) s_rowP[0][wid] = acc;
        __syncthreads();
        if (tid == 0) {
            float s = 0.0f;
#pragma unroll
            for (int i = 0; i < 8; ++i) s += s_rowP[0][i];
            out[0] = s * (1.0f / NN);       // single writer, plain store
            __threadfence();
            g_done = 0;                     // reset for next graph replay
        }
    }
}

// ---------------------------------------------------------------------------
extern "C" void kernel_launch(void* const* d_in, const int* in_sizes, int n_in,
                              void* d_out, int out_size) {
    (void)in_sizes; (void)n_in; (void)out_size;
    const float* x = (const float*)d_in[0];
    float* out = (float*)d_out;

    nt_normalize<<<256, 256>>>(x);

    const int smem = 3 * TILEB;   // 104448 B (A + 2x B)
    cudaFuncSetAttribute(nt_main, cudaFuncAttributeMaxDynamicSharedMemorySize, smem);
    nt_main<<<GRID_MAIN, 256, smem>>>(out);
}